// round 15
// baseline (speedup 1.0000x reference)
#include <cuda_runtime.h>
#include <cstdint>

constexpr int N = 64, C = 256, S = 30, HW = 176;
constexpr int CSTR = S * HW, NSTR = C * CSTR;
constexpr int R = 8, TOPK = 10;
constexpr int H = 8;                      // hw per block: 32B rows, sector-aligned
constexpr int CI = 32, NIT = 8;           // channels per iteration
constexpr int SLOTS = CI + 2 * R;         // 48 (circular halo)
constexpr int P = 12;                     // pitch words: 8 hw + 4 pad, conflict-free
constexpr int SCH = 10, NCH = 3;          // s-chunks for load/compute overlap
// Trim unreachable tail padding of the last row so 3 blocks fit in 227KB/SM.
constexpr int SMEMW = S * SLOTS * P - (P - H);
constexpr int SMEMB = SMEMW * 4;          // 69104 B -> 3 blocks/SM

__device__ float d_g[R + 1];

// g[d] = (1/256)(1 + 2*sum_{k=1..127} e^{-k^2/2048} cos(pi k d/128) + e^{-8} cos(pi d))
__global__ void kinit() {
    const int d = blockIdx.x, t = threadIdx.x;
    const double PI = 3.14159265358979323846;
    double k = (double)(t + 1);
    double term = exp(-k * k / 2048.0) * cos(PI * k * (double)d / 128.0);
    if (t != 127) term *= 2.0;            // Nyquist (k=128) counted once
    __shared__ double red[4];
    #pragma unroll
    for (int o = 16; o; o >>= 1) term += __shfl_down_sync(0xffffffffu, term, o);
    if ((t & 31) == 0) red[t >> 5] = term;
    __syncthreads();
    if (t == 0) d_g[d] = (float)((1.0 + red[0] + red[1] + red[2] + red[3]) / 256.0);
}

__global__ void __launch_bounds__(256, 3)
kfused(const float* __restrict__ seqs, const float* __restrict__ flogit,
       float* __restrict__ out) {
    extern __shared__ float sm[];
    const int hw0 = blockIdx.x * H;
    const int n   = blockIdx.y;
    const int tid = threadIdx.x;
    const int hw  = tid & 7;
    const int cg  = tid >> 3;             // 0..31
    // Permuted channel assignment: warp's 4 cgs -> stride-2 slots (conflict-free
    // LDS banks: slot*12 strides of 24 words -> {0,24,16,8}(+hw) per warp).
    const int cl  = 2 * (cg & 15) + (cg >> 4);   // local channel 0..31
    const float alpha = 1.0f / (1.0f + expf(-flogit[0]));

    float g[R + 1];
    #pragma unroll
    for (int d = 0; d <= R; ++d) g[d] = d_g[d];

    #pragma unroll 1
    for (int it = 0; it < NIT; ++it) {
        const int cb = it * CI + C - R;   // slot -> channel (cb+slot)&255

        // Issue all 3 s-chunk load groups (two 16B cp.asyncs per 32B row;
        // pitch-12 rows are 48B-spaced -> both 16B-aligned).
        // SLOTS*SCH*2 = 960 = 3*256 + 192: 3 uniform rounds + 192-thread tail.
        #pragma unroll
        for (int ck = 0; ck < NCH; ++ck) {
            #pragma unroll
            for (int j = 0; j < 4; ++j) {
                int i = tid + j * 256;
                if (j == 3 && tid >= 192) break;
                int q = i & 1, r = i >> 1;
                int sl = r / SLOTS, slot = r - sl * SLOTS;
                int s = ck * SCH + sl;
                int c = (cb + slot) & 255;
                const float* src = seqs + (size_t)n * NSTR + (size_t)c * CSTR
                                   + s * HW + hw0 + q * 4;
                uint32_t dst = (uint32_t)__cvta_generic_to_shared(
                    sm + (s * SLOTS + slot) * P + q * 4);
                asm volatile("cp.async.cg.shared.global [%0],[%1],16;"
                             :: "r"(dst), "l"(src));
            }
            asm volatile("cp.async.commit_group;" ::: "memory");
        }

        float sc[S], top[TOPK];
        #pragma unroll
        for (int i = 0; i < TOPK; ++i) top[i] = -1.0f;

        // Compute chunk k while chunk k+1 streams in
        #pragma unroll
        for (int ck = 0; ck < NCH; ++ck) {
            if (ck == 0)      asm volatile("cp.async.wait_group 2;" ::: "memory");
            else if (ck == 1) asm volatile("cp.async.wait_group 1;" ::: "memory");
            else              asm volatile("cp.async.wait_group 0;" ::: "memory");
            __syncthreads();

            #pragma unroll
            for (int j = 0; j < SCH; ++j) {
                const int s = ck * SCH + j;
                const float* b = sm + (s * SLOTS + cl) * P + hw;
                float w[2 * R + 1];
                #pragma unroll
                for (int u = 0; u < 2 * R + 1; ++u) w[u] = b[u * P];
                const float x = w[R];
                float acc = g[0] * x;
                #pragma unroll
                for (int d = 1; d <= R; ++d)
                    acc = fmaf(g[d], w[R - d] + w[R + d], acc);
                const float sv = __fdividef(fabsf(acc), fabsf(acc - x) + 1e-6f);
                sc[s] = sv;
                float cr = sv;                 // triangular insertion chain
                #pragma unroll
                for (int i = 0; i < TOPK; ++i) {
                    if (i <= s) {
                        float m = fmaxf(top[i], cr);
                        cr      = fminf(top[i], cr);
                        top[i]  = m;
                    }
                }
            }
        }

        // Threshold; strict-greater count derived from top[] itself:
        // any sc > thr is necessarily one of the kept top-10 entries.
        const float thr = top[TOPK - 1];
        int bud = TOPK;
        #pragma unroll
        for (int i = 0; i < TOPK - 1; ++i) bud -= (top[i] > thr);

        // Stable-tie selection + max pool in one pass
        float sum = 0.0f, mx = -3.0e38f;
        const float* p0 = sm + (cl + R) * P + hw;    // center slot, s=0
        #pragma unroll
        for (int s = 0; s < S; ++s) {
            const float v = *p0;
            p0 += SLOTS * P;
            mx = fmaxf(mx, v);
            bool tk = sc[s] > thr;
            if (sc[s] == thr && bud > 0) { tk = true; --bud; }
            if (tk) sum += v;
        }
        const int c = it * CI + cl;
        out[(n * C + c) * HW + hw0 + hw] =
            alpha * (sum * (1.0f / TOPK)) + (1.0f - alpha) * mx;

        __syncthreads();   // tile reads done before next iteration overwrites
    }
}

extern "C" void kernel_launch(void* const* d_in, const int* in_sizes, int n_in,
                              void* d_out, int out_size) {
    const float* seqs  = (const float*)d_in[0];
    const float* logit = (const float*)d_in[1];
    float* out = (float*)d_out;
    cudaFuncSetAttribute(kfused, cudaFuncAttributeMaxDynamicSharedMemorySize, SMEMB);
    kinit<<<R + 1, 128>>>();
    kfused<<<dim3(HW / H, N), 256, SMEMB>>>(seqs, logit, out);
}

// round 16
// speedup vs baseline: 1.1396x; 1.1396x over previous
#include <cuda_runtime.h>
#include <cstdint>

constexpr int N = 64, C = 256, S = 30, HW = 176;
constexpr int CSTR = S * HW, NSTR = C * CSTR;
constexpr int R = 8, TOPK = 10;
constexpr int H = 8;                      // hw per block: 32B rows, sector-aligned
constexpr int CI = 64, NIT = 4;           // channels per iteration
constexpr int SLOTS = CI + 2 * R;         // 80 (circular halo)
constexpr int P = 12;                     // pitch words: 8 hw + 4 pad, conflict-free
constexpr int SCH = 10, NCH = 3;          // s-chunks for load/compute overlap
constexpr int SHALF = 15;                 // split point for the two top-k chains
// Trim unreachable tail padding of the last row so 2 blocks fit in 227KB/SM.
constexpr int SMEMW = S * SLOTS * P - (P - H);
constexpr int SMEMB = SMEMW * 4;          // 115184 B -> 2 blocks/SM

__device__ float d_g[R + 1];

// g[d] = (1/256)(1 + 2*sum_{k=1..127} e^{-k^2/2048} cos(pi k d/128) + e^{-8} cos(pi d))
__global__ void kinit() {
    const int d = blockIdx.x, t = threadIdx.x;
    const double PI = 3.14159265358979323846;
    double k = (double)(t + 1);
    double term = exp(-k * k / 2048.0) * cos(PI * k * (double)d / 128.0);
    if (t != 127) term *= 2.0;            // Nyquist (k=128) counted once
    __shared__ double red[4];
    #pragma unroll
    for (int o = 16; o; o >>= 1) term += __shfl_down_sync(0xffffffffu, term, o);
    if ((t & 31) == 0) red[t >> 5] = term;
    __syncthreads();
    if (t == 0) d_g[d] = (float)((1.0 + red[0] + red[1] + red[2] + red[3]) / 256.0);
}

__global__ void __launch_bounds__(256, 2)
kfused(const float* __restrict__ seqs, const float* __restrict__ flogit,
       float* __restrict__ out) {
    extern __shared__ float sm[];
    const int hw0 = blockIdx.x * H;
    const int n   = blockIdx.y;
    const int tid = threadIdx.x;
    const int hw  = tid & 7;
    const int cg  = tid >> 3;             // 0..31 -> local channels 2cg, 2cg+1
    const int w0  = 2 * cg;               // window base slot
    const float alpha = 1.0f / (1.0f + expf(-flogit[0]));

    float g[R + 1];
    #pragma unroll
    for (int d = 0; d <= R; ++d) g[d] = d_g[d];

    #pragma unroll 1
    for (int it = 0; it < NIT; ++it) {
        const int cb = it * CI + C - R;   // slot -> channel (cb+slot)&255

        // Issue all 3 s-chunk load groups (two 16B cp.asyncs per 32B row;
        // pitch-12 rows are 48B-spaced -> both 16B-aligned).
        // SLOTS*SCH*2 = 1600 = 6*256 + 64: 6 uniform rounds + 64-thread tail.
        #pragma unroll
        for (int ck = 0; ck < NCH; ++ck) {
            #pragma unroll
            for (int j = 0; j < 7; ++j) {
                int i = tid + j * 256;
                if (j == 6 && tid >= 64) break;
                int q = i & 1, r = i >> 1;
                int sl = r / SLOTS, slot = r - sl * SLOTS;
                int s = ck * SCH + sl;
                int c = (cb + slot) & 255;
                const float* src = seqs + (size_t)n * NSTR + (size_t)c * CSTR
                                   + s * HW + hw0 + q * 4;
                uint32_t dst = (uint32_t)__cvta_generic_to_shared(
                    sm + (s * SLOTS + slot) * P + q * 4);
                asm volatile("cp.async.cg.shared.global [%0],[%1],16;"
                             :: "r"(dst), "l"(src));
            }
            asm volatile("cp.async.commit_group;" ::: "memory");
        }

        float sc[2][S], topA[2][TOPK], topB[2][TOPK];
        #pragma unroll
        for (int ch = 0; ch < 2; ++ch)
            #pragma unroll
            for (int i = 0; i < TOPK; ++i) {
                topA[ch][i] = -1.0f;
                topB[ch][i] = -1.0f;
            }

        // Compute chunk k while chunk k+1 streams in
        #pragma unroll
        for (int ck = 0; ck < NCH; ++ck) {
            if (ck == 0)      asm volatile("cp.async.wait_group 2;" ::: "memory");
            else if (ck == 1) asm volatile("cp.async.wait_group 1;" ::: "memory");
            else              asm volatile("cp.async.wait_group 0;" ::: "memory");
            __syncthreads();

            #pragma unroll
            for (int j = 0; j < SCH; ++j) {
                const int s = ck * SCH + j;
                const float* b = sm + (s * SLOTS + w0) * P + hw;
                float w[2 * R + 2];
                #pragma unroll
                for (int u = 0; u < 2 * R + 2; ++u) w[u] = b[u * P];
                #pragma unroll
                for (int ch = 0; ch < 2; ++ch) {
                    const float x = w[ch + R];
                    float acc = g[0] * x;
                    #pragma unroll
                    for (int d = 1; d <= R; ++d)
                        acc = fmaf(g[d], w[ch + R - d] + w[ch + R + d], acc);
                    const float sv = __fdividef(fabsf(acc), fabsf(acc - x) + 1e-6f);
                    sc[ch][s] = sv;
                    float cr = sv;         // triangular insertion, split chains
                    if (s < SHALF) {
                        #pragma unroll
                        for (int i = 0; i < TOPK; ++i) {
                            if (i <= s) {
                                float m = fmaxf(topA[ch][i], cr);
                                cr      = fminf(topA[ch][i], cr);
                                topA[ch][i] = m;
                            }
                        }
                    } else {
                        #pragma unroll
                        for (int i = 0; i < TOPK; ++i) {
                            if (i <= s - SHALF) {
                                float m = fmaxf(topB[ch][i], cr);
                                cr      = fminf(topB[ch][i], cr);
                                topB[ch][i] = m;
                            }
                        }
                    }
                }
            }
        }

        // Partner-max merge: top-10 of the union of two sorted-desc 10-lists
        // is exactly { max(A[i], B[9-i]) }. thr = min of that set.
        float thr[2]; int bud[2];
        #pragma unroll
        for (int ch = 0; ch < 2; ++ch) {
            float T[TOPK];
            #pragma unroll
            for (int i = 0; i < TOPK; ++i)
                T[i] = fmaxf(topA[ch][i], topB[ch][TOPK - 1 - i]);
            float t01 = fminf(T[0], T[1]), t23 = fminf(T[2], T[3]);
            float t45 = fminf(T[4], T[5]), t67 = fminf(T[6], T[7]);
            float t89 = fminf(T[8], T[9]);
            float th = fminf(fminf(fminf(t01, t23), fminf(t45, t67)), t89);
            thr[ch] = th;
            int bd = TOPK;
            #pragma unroll
            for (int i = 0; i < TOPK; ++i) bd -= (T[i] > th);
            bud[ch] = bd;
        }

        // Single merged pass: stable-tie selection + max pool, both channels
        float sum0 = 0.0f, sum1 = 0.0f, mx0 = -3.0e38f, mx1 = -3.0e38f;
        int bud0 = bud[0], bud1 = bud[1];
        const float thr0 = thr[0], thr1 = thr[1];
        const float* p0 = sm + (w0 + R) * P + hw;      // slot w0+8, s=0
        #pragma unroll
        for (int s = 0; s < S; ++s) {
            const float v0 = p0[0];
            const float v1 = p0[P];                    // slot w0+9
            p0 += SLOTS * P;
            mx0 = fmaxf(mx0, v0);
            mx1 = fmaxf(mx1, v1);
            bool t0 = sc[0][s] > thr0;
            if (sc[0][s] == thr0 && bud0 > 0) { t0 = true; --bud0; }
            if (t0) sum0 += v0;
            bool t1 = sc[1][s] > thr1;
            if (sc[1][s] == thr1 && bud1 > 0) { t1 = true; --bud1; }
            if (t1) sum1 += v1;
        }
        const int c0 = it * CI + 2 * cg;
        out[(n * C + c0) * HW + hw0 + hw] =
            alpha * (sum0 * (1.0f / TOPK)) + (1.0f - alpha) * mx0;
        out[(n * C + c0 + 1) * HW + hw0 + hw] =
            alpha * (sum1 * (1.0f / TOPK)) + (1.0f - alpha) * mx1;

        __syncthreads();   // tile reads done before next iteration overwrites
    }
}

extern "C" void kernel_launch(void* const* d_in, const int* in_sizes, int n_in,
                              void* d_out, int out_size) {
    const float* seqs  = (const float*)d_in[0];
    const float* logit = (const float*)d_in[1];
    float* out = (float*)d_out;
    cudaFuncSetAttribute(kfused, cudaFuncAttributeMaxDynamicSharedMemorySize, SMEMB);
    kinit<<<R + 1, 128>>>();
    kfused<<<dim3(HW / H, N), 256, SMEMB>>>(seqs, logit, out);
}